// round 3
// baseline (speedup 1.0000x reference)
#include <cuda_runtime.h>

#define NPOS 4096
#define NB   4
#define CIN  256
#define DD   64

// Scratch (allocation-free rule: __device__ globals)
__device__ float g_wT[3 * CIN * DD];          // [head][c][o] transposed weights
__device__ float g_q[NB * NPOS * DD];         // [b][n][d]
__device__ float g_k[NB * NPOS * DD];
__device__ float g_v[NB * NPOS * DD];
__device__ float g_o[NB * NPOS * DD];

// ---------------------------------------------------------------------------
// Prep: transpose the three down-projection weights [o][c] -> [c][o]
// ---------------------------------------------------------------------------
__global__ void prep_wT_kernel(const float* __restrict__ wq,
                               const float* __restrict__ wk,
                               const float* __restrict__ wv) {
    int h = blockIdx.x;                      // 0=q 1=k 2=v
    const float* w = (h == 0) ? wq : (h == 1) ? wk : wv;
    int idx = blockIdx.y * 256 + threadIdx.x;    // grid.y = 64 -> 16384 elems
    int c = idx >> 6;
    int o = idx & 63;
    g_wT[h * CIN * DD + c * DD + o] = __ldg(&w[o * CIN + c]);
}

// ---------------------------------------------------------------------------
// Down projections: out[b][n][o] = sum_c x[b][c][n] * w[o][c] + bias[o]
// CTA: one (batch, head, 64-wide n tile). 256 thr, 4n x 4o micro-tile.
// ---------------------------------------------------------------------------
__global__ __launch_bounds__(256) void proj_kernel(
    const float* __restrict__ x,
    const float* __restrict__ bq,
    const float* __restrict__ bk,
    const float* __restrict__ bv) {
    __shared__ float Xs[64][68];   // [c][n]
    __shared__ float Ws[64][68];   // [c][o]

    int n0 = blockIdx.x * 64;
    int h  = blockIdx.y;
    int b  = blockIdx.z;
    const float* bias = (h == 0) ? bq : (h == 1) ? bk : bv;
    float* out = (h == 0) ? g_q : (h == 1) ? g_k : g_v;

    int t  = threadIdx.x;
    int to = t & 15;      // o quad (store-contiguous dim)
    int tn = t >> 4;      // n quad

    float acc[4][4];      // [n][o]
    #pragma unroll
    for (int a = 0; a < 4; a++)
        #pragma unroll
        for (int c = 0; c < 4; c++) acc[a][c] = 0.f;

    for (int c0 = 0; c0 < CIN; c0 += 64) {
        __syncthreads();
        #pragma unroll
        for (int i = t; i < 64 * 16; i += 256) {
            int r = i >> 4, c4 = i & 15;
            *(float4*)&Xs[r][c4 * 4] =
                *(const float4*)&x[((size_t)b * CIN + c0 + r) * NPOS + n0 + c4 * 4];
            *(float4*)&Ws[r][c4 * 4] =
                *(const float4*)&g_wT[(h * CIN + c0 + r) * DD + c4 * 4];
        }
        __syncthreads();

        #pragma unroll 8
        for (int c = 0; c < 64; c++) {
            float4 xv = *(const float4*)&Xs[c][tn * 4];
            float4 wv = *(const float4*)&Ws[c][to * 4];
            float xa[4] = {xv.x, xv.y, xv.z, xv.w};
            float wa[4] = {wv.x, wv.y, wv.z, wv.w};
            #pragma unroll
            for (int a = 0; a < 4; a++)
                #pragma unroll
                for (int o = 0; o < 4; o++)
                    acc[a][o] += xa[a] * wa[o];
        }
    }

    float4 b4 = *(const float4*)&bias[to * 4];
    float ba[4] = {b4.x, b4.y, b4.z, b4.w};
    #pragma unroll
    for (int a = 0; a < 4; a++) {
        float4 o4 = make_float4(acc[a][0] + ba[0], acc[a][1] + ba[1],
                                acc[a][2] + ba[2], acc[a][3] + ba[3]);
        *(float4*)&out[((size_t)b * NPOS + n0 + tn * 4 + a) * DD + to * 4] = o4;
    }
}

// ---------------------------------------------------------------------------
// Flash attention: per CTA one (batch, 64-query tile), loop 64-key tiles,
// online softmax. Thread (ti,tj): 4 q-rows x 4 (k or d) cols.
// ---------------------------------------------------------------------------
__global__ __launch_bounds__(256) void attn_kernel() {
    extern __shared__ float sm[];
    float (*Qs)[68] = (float(*)[68])(sm);
    float (*Ks)[68] = (float(*)[68])(sm + 64 * 68);
    float (*Vs)[68] = (float(*)[68])(sm + 2 * 64 * 68);
    float (*Ps)[68] = (float(*)[68])(sm + 3 * 64 * 68);

    int b  = blockIdx.y;
    int q0 = blockIdx.x * 64;
    int t  = threadIdx.x;
    int tj = t & 15;     // key-quad in S phase, d-quad in O phase
    int ti = t >> 4;     // query-quad

    const float* Qg = g_q + (size_t)b * NPOS * DD;
    const float* Kg = g_k + (size_t)b * NPOS * DD;
    const float* Vg = g_v + (size_t)b * NPOS * DD;

    #pragma unroll
    for (int i = t; i < 64 * 16; i += 256) {
        int r = i >> 4, c4 = i & 15;
        *(float4*)&Qs[r][c4 * 4] = *(const float4*)&Qg[(q0 + r) * DD + c4 * 4];
    }

    float m_run[4], l_run[4], O[4][4];
    #pragma unroll
    for (int a = 0; a < 4; a++) {
        m_run[a] = -1e30f;
        l_run[a] = 0.f;
        #pragma unroll
        for (int c = 0; c < 4; c++) O[a][c] = 0.f;
    }

    for (int k0 = 0; k0 < NPOS; k0 += 64) {
        __syncthreads();
        #pragma unroll
        for (int i = t; i < 64 * 16; i += 256) {
            int r = i >> 4, c4 = i & 15;
            *(float4*)&Ks[r][c4 * 4] = *(const float4*)&Kg[(k0 + r) * DD + c4 * 4];
            *(float4*)&Vs[r][c4 * 4] = *(const float4*)&Vg[(k0 + r) * DD + c4 * 4];
        }
        __syncthreads();

        // --- S = Q K^T for this tile ---
        float s[4][4];
        #pragma unroll
        for (int a = 0; a < 4; a++)
            #pragma unroll
            for (int c = 0; c < 4; c++) s[a][c] = 0.f;

        #pragma unroll 4
        for (int d = 0; d < DD; d += 4) {
            float4 qv[4], kv[4];
            #pragma unroll
            for (int a = 0; a < 4; a++) qv[a] = *(const float4*)&Qs[ti * 4 + a][d];
            #pragma unroll
            for (int c = 0; c < 4; c++) kv[c] = *(const float4*)&Ks[tj * 4 + c][d];
            #pragma unroll
            for (int a = 0; a < 4; a++)
                #pragma unroll
                for (int c = 0; c < 4; c++)
                    s[a][c] += qv[a].x * kv[c].x + qv[a].y * kv[c].y +
                               qv[a].z * kv[c].z + qv[a].w * kv[c].w;
        }

        // --- per-row online softmax stats (reduce over 16 tj lanes) ---
        float alpha[4];
        #pragma unroll
        for (int a = 0; a < 4; a++) {
            float m = fmaxf(fmaxf(s[a][0], s[a][1]), fmaxf(s[a][2], s[a][3]));
            #pragma unroll
            for (int off = 8; off >= 1; off >>= 1)
                m = fmaxf(m, __shfl_xor_sync(0xffffffffu, m, off));
            float m_new = fmaxf(m_run[a], m);
            alpha[a] = __expf(m_run[a] - m_new);
            m_run[a] = m_new;
            float lsum = 0.f;
            #pragma unroll
            for (int c = 0; c < 4; c++) {
                s[a][c] = __expf(s[a][c] - m_new);
                lsum += s[a][c];
            }
            #pragma unroll
            for (int off = 8; off >= 1; off >>= 1)
                lsum += __shfl_xor_sync(0xffffffffu, lsum, off);
            l_run[a] = l_run[a] * alpha[a] + lsum;
            *(float4*)&Ps[ti * 4 + a][tj * 4] =
                make_float4(s[a][0], s[a][1], s[a][2], s[a][3]);
        }
        __syncthreads();

        // --- O = O*alpha + P @ V (vectorized P reads: float4 per key-quad) ---
        #pragma unroll
        for (int a = 0; a < 4; a++)
            #pragma unroll
            for (int c = 0; c < 4; c++) O[a][c] *= alpha[a];

        #pragma unroll 4
        for (int kq = 0; kq < 16; kq++) {
            float4 vv[4];
            #pragma unroll
            for (int c = 0; c < 4; c++)
                vv[c] = *(const float4*)&Vs[kq * 4 + c][tj * 4];
            #pragma unroll
            for (int a = 0; a < 4; a++) {
                float4 pv = *(const float4*)&Ps[ti * 4 + a][kq * 4];
                O[a][0] += pv.x * vv[0].x + pv.y * vv[1].x + pv.z * vv[2].x + pv.w * vv[3].x;
                O[a][1] += pv.x * vv[0].y + pv.y * vv[1].y + pv.z * vv[2].y + pv.w * vv[3].y;
                O[a][2] += pv.x * vv[0].z + pv.y * vv[1].z + pv.z * vv[2].z + pv.w * vv[3].z;
                O[a][3] += pv.x * vv[0].w + pv.y * vv[1].w + pv.z * vv[2].w + pv.w * vv[3].w;
            }
        }
    }

    float* Og = g_o + (size_t)b * NPOS * DD;
    #pragma unroll
    for (int a = 0; a < 4; a++) {
        float inv = 1.f / l_run[a];
        *(float4*)&Og[(q0 + ti * 4 + a) * DD + tj * 4] =
            make_float4(O[a][0] * inv, O[a][1] * inv, O[a][2] * inv, O[a][3] * inv);
    }
}

// ---------------------------------------------------------------------------
// Up projection + bias + residual:
// out[b][c][n] = x[b][c][n] + sum_d w_u[c][d] * g_o[b][n][d] + b_u[c]
// ---------------------------------------------------------------------------
__global__ __launch_bounds__(256) void up_kernel(
    const float* __restrict__ x,
    const float* __restrict__ wu,
    const float* __restrict__ bu,
    float* __restrict__ out) {
    __shared__ float Os[64][68];    // [n][d]
    __shared__ float Wus[64][68];   // [c][d]

    int n0 = blockIdx.x * 64;
    int c0 = blockIdx.y * 64;
    int b  = blockIdx.z;
    int t  = threadIdx.x;
    int tn = t & 15;    // n quad (store-contiguous)
    int tc = t >> 4;    // c quad

    #pragma unroll
    for (int i = t; i < 64 * 16; i += 256) {
        int r = i >> 4, c4 = i & 15;
        *(float4*)&Os[r][c4 * 4] =
            *(const float4*)&g_o[((size_t)b * NPOS + n0 + r) * DD + c4 * 4];
        *(float4*)&Wus[r][c4 * 4] = *(const float4*)&wu[(c0 + r) * DD + c4 * 4];
    }
    __syncthreads();

    float acc[4][4];   // [c][n]
    #pragma unroll
    for (int a = 0; a < 4; a++)
        #pragma unroll
        for (int c = 0; c < 4; c++) acc[a][c] = 0.f;

    #pragma unroll 4
    for (int d = 0; d < DD; d += 4) {
        float4 wv[4], ov[4];
        #pragma unroll
        for (int a = 0; a < 4; a++) wv[a] = *(const float4*)&Wus[tc * 4 + a][d];
        #pragma unroll
        for (int c = 0; c < 4; c++) ov[c] = *(const float4*)&Os[tn * 4 + c][d];
        #pragma unroll
        for (int a = 0; a < 4; a++)
            #pragma unroll
            for (int c = 0; c < 4; c++)
                acc[a][c] += wv[a].x * ov[c].x + wv[a].y * ov[c].y +
                             wv[a].z * ov[c].z + wv[a].w * ov[c].w;
    }

    #pragma unroll
    for (int a = 0; a < 4; a++) {
        int c = c0 + tc * 4 + a;
        float bias = __ldg(&bu[c]);
        size_t base = ((size_t)b * CIN + c) * NPOS + n0 + tn * 4;
        float4 xr = *(const float4*)&x[base];
        *(float4*)&out[base] = make_float4(acc[a][0] + bias + xr.x,
                                           acc[a][1] + bias + xr.y,
                                           acc[a][2] + bias + xr.z,
                                           acc[a][3] + bias + xr.w);
    }
}

// ---------------------------------------------------------------------------
extern "C" void kernel_launch(void* const* d_in, const int* in_sizes, int n_in,
                              void* d_out, int out_size) {
    const float* x   = (const float*)d_in[0];
    const float* w_k = (const float*)d_in[1];
    const float* b_k = (const float*)d_in[2];
    const float* w_q = (const float*)d_in[3];
    const float* b_q = (const float*)d_in[4];
    const float* w_v = (const float*)d_in[5];
    const float* b_v = (const float*)d_in[6];
    const float* w_u = (const float*)d_in[7];
    const float* b_u = (const float*)d_in[8];
    float* out = (float*)d_out;

    const int attn_smem = 4 * 64 * 68 * (int)sizeof(float);  // 69632 B
    cudaFuncSetAttribute(attn_kernel,
                         cudaFuncAttributeMaxDynamicSharedMemorySize, attn_smem);

    prep_wT_kernel<<<dim3(3, 64), 256>>>(w_q, w_k, w_v);
    proj_kernel<<<dim3(64, 3, NB), 256>>>(x, b_q, b_k, b_v);
    attn_kernel<<<dim3(64, NB), 256, attn_smem>>>();
    up_kernel<<<dim3(64, 4, NB), 256>>>(x, w_u, b_u, out);
}

// round 4
// speedup vs baseline: 1.6730x; 1.6730x over previous
#include <cuda_runtime.h>

#define NPOS 4096
#define NB   4
#define CIN  256
#define DD   64

// Scratch (allocation-free rule: __device__ globals)
__device__ float g_wT[3 * CIN * DD];          // [head][c][o] transposed weights
__device__ float g_q[NB * NPOS * DD];         // [b][n][d]
__device__ float g_k[NB * NPOS * DD];
__device__ float g_v[NB * NPOS * DD];
__device__ float g_o[NB * NPOS * DD];

// ---- packed f32x2 helpers (Blackwell: FFMA2 only reachable via PTX) ----
__device__ __forceinline__ void ffma2(unsigned long long& acc,
                                      unsigned long long a,
                                      unsigned long long b) {
    asm("fma.rn.f32x2 %0, %1, %2, %0;" : "+l"(acc) : "l"(a), "l"(b));
}
__device__ __forceinline__ void fmul2(unsigned long long& x, unsigned long long m) {
    asm("mul.rn.f32x2 %0, %0, %1;" : "+l"(x) : "l"(m));
}
__device__ __forceinline__ unsigned long long fdup(float v) {
    unsigned long long r;
    asm("mov.b64 %0, {%1, %1};" : "=l"(r) : "f"(v));
    return r;
}
__device__ __forceinline__ float2 funpack(unsigned long long v) {
    float2 f;
    asm("mov.b64 {%0, %1}, %2;" : "=f"(f.x), "=f"(f.y) : "l"(v));
    return f;
}

// ---------------------------------------------------------------------------
// Prep: transpose the three down-projection weights [o][c] -> [c][o]
// ---------------------------------------------------------------------------
__global__ void prep_wT_kernel(const float* __restrict__ wq,
                               const float* __restrict__ wk,
                               const float* __restrict__ wv) {
    int h = blockIdx.x;                      // 0=q 1=k 2=v
    const float* w = (h == 0) ? wq : (h == 1) ? wk : wv;
    int idx = blockIdx.y * 256 + threadIdx.x;
    int c = idx >> 6;
    int o = idx & 63;
    g_wT[h * CIN * DD + c * DD + o] = __ldg(&w[o * CIN + c]);
}

// ---------------------------------------------------------------------------
// Down projections: out[b][n][o] = sum_c x[b][c][n] * w[o][c] + bias[o]
// (no bank conflicts here: inner loads are same-row broadcast/contiguous)
// ---------------------------------------------------------------------------
__global__ __launch_bounds__(256) void proj_kernel(
    const float* __restrict__ x,
    const float* __restrict__ bq,
    const float* __restrict__ bk,
    const float* __restrict__ bv) {
    __shared__ float Xs[64][68];   // [c][n]
    __shared__ float Ws[64][68];   // [c][o]

    int n0 = blockIdx.x * 64;
    int h  = blockIdx.y;
    int b  = blockIdx.z;
    const float* bias = (h == 0) ? bq : (h == 1) ? bk : bv;
    float* out = (h == 0) ? g_q : (h == 1) ? g_k : g_v;

    int t  = threadIdx.x;
    int to = t & 15;      // o quad (store-contiguous dim)
    int tn = t >> 4;      // n quad

    float acc[4][4];      // [n][o]
    #pragma unroll
    for (int a = 0; a < 4; a++)
        #pragma unroll
        for (int c = 0; c < 4; c++) acc[a][c] = 0.f;

    for (int c0 = 0; c0 < CIN; c0 += 64) {
        __syncthreads();
        #pragma unroll
        for (int i = t; i < 64 * 16; i += 256) {
            int r = i >> 4, c4 = i & 15;
            *(float4*)&Xs[r][c4 * 4] =
                *(const float4*)&x[((size_t)b * CIN + c0 + r) * NPOS + n0 + c4 * 4];
            *(float4*)&Ws[r][c4 * 4] =
                *(const float4*)&g_wT[(h * CIN + c0 + r) * DD + c4 * 4];
        }
        __syncthreads();

        #pragma unroll 8
        for (int c = 0; c < 64; c++) {
            float4 xv = *(const float4*)&Xs[c][tn * 4];
            float4 wv = *(const float4*)&Ws[c][to * 4];
            float xa[4] = {xv.x, xv.y, xv.z, xv.w};
            float wa[4] = {wv.x, wv.y, wv.z, wv.w};
            #pragma unroll
            for (int a = 0; a < 4; a++)
                #pragma unroll
                for (int o = 0; o < 4; o++)
                    acc[a][o] += xa[a] * wa[o];
        }
    }

    float4 b4 = *(const float4*)&bias[to * 4];
    float ba[4] = {b4.x, b4.y, b4.z, b4.w};
    #pragma unroll
    for (int a = 0; a < 4; a++) {
        float4 o4 = make_float4(acc[a][0] + ba[0], acc[a][1] + ba[1],
                                acc[a][2] + ba[2], acc[a][3] + ba[3]);
        *(float4*)&out[((size_t)b * NPOS + n0 + tn * 4 + a) * DD + to * 4] = o4;
    }
}

// ---------------------------------------------------------------------------
// Flash attention. Thread (ti,tj):
//   S-phase: q-rows {4ti..4ti+3} x keys {tj, tj+16, tj+32, tj+48}
//            (key stride 16 -> K row reads hit all 8 smem superbanks)
//   O-phase: q-rows {4ti..} x d-cols {4tj..4tj+3}
// Accumulation packed f32x2 over d (S) / over d-cols (O).
// ---------------------------------------------------------------------------
__global__ __launch_bounds__(256) void attn_kernel() {
    extern __shared__ float sm[];
    float (*Qs)[68] = (float(*)[68])(sm);
    float (*Ks)[68] = (float(*)[68])(sm + 64 * 68);
    float (*Vs)[68] = (float(*)[68])(sm + 2 * 64 * 68);
    float (*Ps)[68] = (float(*)[68])(sm + 3 * 64 * 68);

    int b  = blockIdx.y;
    int q0 = blockIdx.x * 64;
    int t  = threadIdx.x;
    int tj = t & 15;
    int ti = t >> 4;

    const float* Qg = g_q + (size_t)b * NPOS * DD;
    const float* Kg = g_k + (size_t)b * NPOS * DD;
    const float* Vg = g_v + (size_t)b * NPOS * DD;

    #pragma unroll
    for (int i = t; i < 64 * 16; i += 256) {
        int r = i >> 4, c4 = i & 15;
        *(float4*)&Qs[r][c4 * 4] = *(const float4*)&Qg[(q0 + r) * DD + c4 * 4];
    }

    float m_run[4], l_run[4];
    unsigned long long O2[4][2];          // packed over d-cols {4tj,4tj+1},{4tj+2,4tj+3}
    #pragma unroll
    for (int a = 0; a < 4; a++) {
        m_run[a] = -1e30f;
        l_run[a] = 0.f;
        O2[a][0] = 0ull; O2[a][1] = 0ull;
    }

    for (int k0 = 0; k0 < NPOS; k0 += 64) {
        __syncthreads();
        #pragma unroll
        for (int i = t; i < 64 * 16; i += 256) {
            int r = i >> 4, c4 = i & 15;
            *(float4*)&Ks[r][c4 * 4] = *(const float4*)&Kg[(k0 + r) * DD + c4 * 4];
            *(float4*)&Vs[r][c4 * 4] = *(const float4*)&Vg[(k0 + r) * DD + c4 * 4];
        }
        __syncthreads();

        // --- S = Q K^T, f32x2 packed over d ---
        unsigned long long s2[4][4];
        #pragma unroll
        for (int a = 0; a < 4; a++)
            #pragma unroll
            for (int c = 0; c < 4; c++) s2[a][c] = 0ull;

        #pragma unroll 4
        for (int d = 0; d < DD; d += 4) {
            ulonglong2 q2[4], k2[4];
            #pragma unroll
            for (int a = 0; a < 4; a++)
                q2[a] = *(const ulonglong2*)&Qs[ti * 4 + a][d];
            #pragma unroll
            for (int c = 0; c < 4; c++)
                k2[c] = *(const ulonglong2*)&Ks[tj + 16 * c][d];
            #pragma unroll
            for (int a = 0; a < 4; a++)
                #pragma unroll
                for (int c = 0; c < 4; c++) {
                    ffma2(s2[a][c], q2[a].x, k2[c].x);
                    ffma2(s2[a][c], q2[a].y, k2[c].y);
                }
        }

        float s[4][4];
        #pragma unroll
        for (int a = 0; a < 4; a++)
            #pragma unroll
            for (int c = 0; c < 4; c++) {
                float2 f = funpack(s2[a][c]);
                s[a][c] = f.x + f.y;
            }

        // --- per-row online softmax stats (reduce over 16 tj lanes) ---
        float alpha[4];
        #pragma unroll
        for (int a = 0; a < 4; a++) {
            float m = fmaxf(fmaxf(s[a][0], s[a][1]), fmaxf(s[a][2], s[a][3]));
            #pragma unroll
            for (int off = 8; off >= 1; off >>= 1)
                m = fmaxf(m, __shfl_xor_sync(0xffffffffu, m, off));
            float m_new = fmaxf(m_run[a], m);
            alpha[a] = __expf(m_run[a] - m_new);
            m_run[a] = m_new;
            float lsum = 0.f;
            #pragma unroll
            for (int c = 0; c < 4; c++) {
                s[a][c] = __expf(s[a][c] - m_new);
                lsum += s[a][c];
            }
            #pragma unroll
            for (int off = 8; off >= 1; off >>= 1)
                lsum += __shfl_xor_sync(0xffffffffu, lsum, off);
            l_run[a] = l_run[a] * alpha[a] + lsum;
            #pragma unroll
            for (int c = 0; c < 4; c++)
                Ps[ti * 4 + a][tj + 16 * c] = s[a][c];   // 32 distinct banks: conflict-free
        }
        __syncthreads();

        // --- O = O*alpha + P @ V, f32x2 packed over d-cols ---
        #pragma unroll
        for (int a = 0; a < 4; a++) {
            unsigned long long am = fdup(alpha[a]);
            fmul2(O2[a][0], am);
            fmul2(O2[a][1], am);
        }

        #pragma unroll 4
        for (int kq = 0; kq < 16; kq++) {
            ulonglong2 v2[4];
            #pragma unroll
            for (int c = 0; c < 4; c++)
                v2[c] = *(const ulonglong2*)&Vs[kq * 4 + c][tj * 4];
            #pragma unroll
            for (int a = 0; a < 4; a++) {
                float4 pv = *(const float4*)&Ps[ti * 4 + a][kq * 4];
                unsigned long long p0 = fdup(pv.x), p1 = fdup(pv.y),
                                   p2 = fdup(pv.z), p3 = fdup(pv.w);
                ffma2(O2[a][0], p0, v2[0].x); ffma2(O2[a][1], p0, v2[0].y);
                ffma2(O2[a][0], p1, v2[1].x); ffma2(O2[a][1], p1, v2[1].y);
                ffma2(O2[a][0], p2, v2[2].x); ffma2(O2[a][1], p2, v2[2].y);
                ffma2(O2[a][0], p3, v2[3].x); ffma2(O2[a][1], p3, v2[3].y);
            }
        }
    }

    float* Og = g_o + (size_t)b * NPOS * DD;
    #pragma unroll
    for (int a = 0; a < 4; a++) {
        float inv = 1.f / l_run[a];
        float2 lo = funpack(O2[a][0]);
        float2 hi = funpack(O2[a][1]);
        *(float4*)&Og[(q0 + ti * 4 + a) * DD + tj * 4] =
            make_float4(lo.x * inv, lo.y * inv, hi.x * inv, hi.y * inv);
    }
}

// ---------------------------------------------------------------------------
// Up projection + bias + residual (conflict-free remap: n columns tn+16c)
// ---------------------------------------------------------------------------
__global__ __launch_bounds__(256) void up_kernel(
    const float* __restrict__ x,
    const float* __restrict__ wu,
    const float* __restrict__ bu,
    float* __restrict__ out) {
    __shared__ float Os[64][68];    // [n][d]
    __shared__ float Wus[64][68];   // [c][d]

    int n0 = blockIdx.x * 64;
    int c0 = blockIdx.y * 64;
    int b  = blockIdx.z;
    int t  = threadIdx.x;
    int tn = t & 15;    // n lane: columns {tn, tn+16, tn+32, tn+48}
    int tc = t >> 4;    // c quad

    #pragma unroll
    for (int i = t; i < 64 * 16; i += 256) {
        int r = i >> 4, c4 = i & 15;
        *(float4*)&Os[r][c4 * 4] =
            *(const float4*)&g_o[((size_t)b * NPOS + n0 + r) * DD + c4 * 4];
        *(float4*)&Wus[r][c4 * 4] = *(const float4*)&wu[(c0 + r) * DD + c4 * 4];
    }
    __syncthreads();

    float acc[4][4];   // [c][n]
    #pragma unroll
    for (int a = 0; a < 4; a++)
        #pragma unroll
        for (int c = 0; c < 4; c++) acc[a][c] = 0.f;

    #pragma unroll 4
    for (int d = 0; d < DD; d += 4) {
        float4 wv[4], ov[4];
        #pragma unroll
        for (int a = 0; a < 4; a++) wv[a] = *(const float4*)&Wus[tc * 4 + a][d];
        #pragma unroll
        for (int c = 0; c < 4; c++) ov[c] = *(const float4*)&Os[tn + 16 * c][d];
        #pragma unroll
        for (int a = 0; a < 4; a++)
            #pragma unroll
            for (int c = 0; c < 4; c++)
                acc[a][c] += wv[a].x * ov[c].x + wv[a].y * ov[c].y +
                             wv[a].z * ov[c].z + wv[a].w * ov[c].w;
    }

    #pragma unroll
    for (int a = 0; a < 4; a++) {
        int ch = c0 + tc * 4 + a;
        float bias = __ldg(&bu[ch]);
        size_t base = ((size_t)b * CIN + ch) * NPOS + n0;
        #pragma unroll
        for (int c = 0; c < 4; c++) {
            int n = tn + 16 * c;
            out[base + n] = acc[a][c] + bias + x[base + n];
        }
    }
}

// ---------------------------------------------------------------------------
extern "C" void kernel_launch(void* const* d_in, const int* in_sizes, int n_in,
                              void* d_out, int out_size) {
    const float* x   = (const float*)d_in[0];
    const float* w_k = (const float*)d_in[1];
    const float* b_k = (const float*)d_in[2];
    const float* w_q = (const float*)d_in[3];
    const float* b_q = (const float*)d_in[4];
    const float* w_v = (const float*)d_in[5];
    const float* b_v = (const float*)d_in[6];
    const float* w_u = (const float*)d_in[7];
    const float* b_u = (const float*)d_in[8];
    float* out = (float*)d_out;

    const int attn_smem = 4 * 64 * 68 * (int)sizeof(float);  // 69632 B
    cudaFuncSetAttribute(attn_kernel,
                         cudaFuncAttributeMaxDynamicSharedMemorySize, attn_smem);

    prep_wT_kernel<<<dim3(3, 64), 256>>>(w_q, w_k, w_v);
    proj_kernel<<<dim3(64, 3, NB), 256>>>(x, b_q, b_k, b_v);
    attn_kernel<<<dim3(64, NB), 256, attn_smem>>>();
    up_kernel<<<dim3(64, 4, NB), 256>>>(x, w_u, b_u, out);
}